// round 1
// baseline (speedup 1.0000x reference)
#include <cuda_runtime.h>
#include <math.h>

#define N_NODES 8192
#define IN_F    512
#define OUT_F   256

// Intermediate: support = input @ weight  [8192, 256] fp32 = 8 MB
__device__ float g_support[N_NODES * OUT_F];

// Tiled SGEMM: C[M,Ncols] = op(A)[M,K] @ B[K,Ncols] (+ bias, ELU)
// BM=BN=64, BK=16, 256 threads, each thread computes 4x4.
// SQ:  square A elements on load (adj ** 2)
// EPI: add bias + ELU epilogue
template <bool SQ, bool EPI>
__global__ __launch_bounds__(256)
void gemm64_kernel(const float* __restrict__ A,
                   const float* __restrict__ B,
                   const float* __restrict__ bias,
                   float* __restrict__ C,
                   int M, int K, int Ncols)
{
    __shared__ float As[16][65];   // transposed A tile, pad 1 to kill bank conflicts
    __shared__ float Bs[16][64];

    const int tid = threadIdx.x;
    const int bm = blockIdx.y * 64;
    const int bn = blockIdx.x * 64;

    // compute-thread mapping: 16x16 thread grid, 4x4 micro-tile
    const int trow = (tid >> 4) * 4;   // 0..60
    const int tcol = (tid & 15) * 4;   // 0..60

    // A-load mapping: 64 rows x 4 float4-chunks of K
    const int arow = tid >> 2;         // 0..63
    const int akg  = (tid & 3) * 4;    // 0,4,8,12

    // B-load mapping: 16 rows x 16 float4-chunks of N
    const int brow = tid >> 4;         // 0..15
    const int bcol = (tid & 15) * 4;   // 0..60

    float acc[4][4];
#pragma unroll
    for (int i = 0; i < 4; i++)
#pragma unroll
        for (int j = 0; j < 4; j++) acc[i][j] = 0.0f;

    const float* Aptr = A + (size_t)(bm + arow) * K + akg;
    const float* Bptr = B + (size_t)brow * Ncols + bn + bcol;

    for (int kt = 0; kt < K; kt += 16) {
        // load A tile (coalesced float4 along K), square if requested, store transposed
        float4 av = *reinterpret_cast<const float4*>(Aptr + kt);
        if (SQ) {
            av.x *= av.x; av.y *= av.y; av.z *= av.z; av.w *= av.w;
        }
        As[akg + 0][arow] = av.x;
        As[akg + 1][arow] = av.y;
        As[akg + 2][arow] = av.z;
        As[akg + 3][arow] = av.w;

        // load B tile (coalesced float4 along N)
        float4 bv = *reinterpret_cast<const float4*>(Bptr + (size_t)kt * Ncols);
        *reinterpret_cast<float4*>(&Bs[brow][bcol]) = bv;

        __syncthreads();

#pragma unroll
        for (int kk = 0; kk < 16; kk++) {
            const float a0 = As[kk][trow + 0];
            const float a1 = As[kk][trow + 1];
            const float a2 = As[kk][trow + 2];
            const float a3 = As[kk][trow + 3];
            const float4 b = *reinterpret_cast<const float4*>(&Bs[kk][tcol]);
            acc[0][0] += a0 * b.x; acc[0][1] += a0 * b.y; acc[0][2] += a0 * b.z; acc[0][3] += a0 * b.w;
            acc[1][0] += a1 * b.x; acc[1][1] += a1 * b.y; acc[1][2] += a1 * b.z; acc[1][3] += a1 * b.w;
            acc[2][0] += a2 * b.x; acc[2][1] += a2 * b.y; acc[2][2] += a2 * b.z; acc[2][3] += a2 * b.w;
            acc[3][0] += a3 * b.x; acc[3][1] += a3 * b.y; acc[3][2] += a3 * b.z; acc[3][3] += a3 * b.w;
        }

        __syncthreads();
    }

    // epilogue
    float4 bvals;
    if (EPI) {
        bvals = *reinterpret_cast<const float4*>(bias + bn + tcol);
    }

#pragma unroll
    for (int i = 0; i < 4; i++) {
        float4 v;
        v.x = acc[i][0]; v.y = acc[i][1]; v.z = acc[i][2]; v.w = acc[i][3];
        if (EPI) {
            v.x += bvals.x; v.y += bvals.y; v.z += bvals.z; v.w += bvals.w;
            v.x = v.x > 0.0f ? v.x : expm1f(v.x);
            v.y = v.y > 0.0f ? v.y : expm1f(v.y);
            v.z = v.z > 0.0f ? v.z : expm1f(v.z);
            v.w = v.w > 0.0f ? v.w : expm1f(v.w);
        }
        *reinterpret_cast<float4*>(C + (size_t)(bm + trow + i) * Ncols + bn + tcol) = v;
    }
}

extern "C" void kernel_launch(void* const* d_in, const int* in_sizes, int n_in,
                              void* d_out, int out_size)
{
    const float* input  = (const float*)d_in[0];  // [8192, 512]
    const float* adj    = (const float*)d_in[1];  // [8192, 8192]
    const float* weight = (const float*)d_in[2];  // [512, 256]
    const float* bias   = (const float*)d_in[3];  // [256]
    float* out = (float*)d_out;                   // [8192, 256]

    float* support = nullptr;
    cudaGetSymbolAddress((void**)&support, g_support);

    // GEMM 1: support = input @ weight   (8192 x 512 x 256)
    {
        dim3 grid(OUT_F / 64, N_NODES / 64);
        gemm64_kernel<false, false><<<grid, 256>>>(input, weight, nullptr, support,
                                                   N_NODES, IN_F, OUT_F);
    }

    // GEMM 2: out = ELU( (adj**2) @ support + bias )   (8192 x 8192 x 256)
    {
        dim3 grid(OUT_F / 64, N_NODES / 64);
        gemm64_kernel<true, true><<<grid, 256>>>(adj, support, bias, out,
                                                 N_NODES, N_NODES, OUT_F);
    }
}

// round 3
// speedup vs baseline: 2.7858x; 2.7858x over previous
#include <cuda_runtime.h>
#include <cuda_bf16.h>
#include <stdint.h>
#include <math.h>

#define N_NODES 8192
#define IN_F    512
#define OUT_F   256

// Intermediate: support = input @ weight  [8192, 256] fp32 = 8 MB
__device__ float g_support[N_NODES * OUT_F];

// Tiles
#define BM 128
#define BN 128
#define BK 64
#define PITCH    72                 // bf16 elems per smem row (64 + 8 pad)
#define PITCH_B  (PITCH * 2)        // 144 bytes
#define TILE_BYTES  (128 * PITCH_B) // 18432 (one 128x64 bf16 tile)
#define STAGE_BYTES (4 * TILE_BYTES)
#define SMEM_BYTES  (2 * STAGE_BYTES) // 147456

__device__ __forceinline__ void mma16816(float c[4],
                                         uint32_t a0, uint32_t a1, uint32_t a2, uint32_t a3,
                                         uint32_t b0, uint32_t b1) {
    asm volatile(
        "mma.sync.aligned.m16n8k16.row.col.f32.bf16.bf16.f32 "
        "{%0,%1,%2,%3}, {%4,%5,%6,%7}, {%8,%9}, {%0,%1,%2,%3};"
        : "+f"(c[0]), "+f"(c[1]), "+f"(c[2]), "+f"(c[3])
        : "r"(a0), "r"(a1), "r"(a2), "r"(a3), "r"(b0), "r"(b1));
}

// split (x,y) into packed bf16x2 hi and lo parts
__device__ __forceinline__ void split2(float x, float y, uint32_t& hi, uint32_t& lo) {
    __nv_bfloat162 h = __floats2bfloat162_rn(x, y);
    float2 hf = __bfloat1622float2(h);
    __nv_bfloat162 l = __floats2bfloat162_rn(x - hf.x, y - hf.y);
    hi = *reinterpret_cast<uint32_t*>(&h);
    lo = *reinterpret_cast<uint32_t*>(&l);
}

// C[128,128] tile = op(A)[128,K] @ B[K,128] via 2-term bf16 split (3 mmas).
// A smem: [m][k] (k contig). B smem: [n][k] (k contig, i.e. transposed on load).
// SQ: square A on load (adj**2). EPI: bias + ELU.
template <bool SQ, bool EPI>
__global__ __launch_bounds__(256, 1)
void mma_gemm(const float* __restrict__ A, const float* __restrict__ B,
              const float* __restrict__ bias, float* __restrict__ C,
              int K, int lda, int ldb, int ldc)
{
    extern __shared__ __align__(16) char smem[];
    const int tid = threadIdx.x;
    const int bm = blockIdx.y * BM;
    const int bn = blockIdx.x * BN;
    const int wid = tid >> 5, lid = tid & 31;
    const int wm = (wid & 1) * 64;        // warp M offset
    const int wn = (wid >> 1) * 32;       // warp N offset
    const int grp = lid >> 2, quad = lid & 3;

    // global-load mappings
    const int a_row = tid >> 1, a_k4b = tid & 1;     // A: row, float4-chunk parity
    const int b_n = tid & 127, b_kqb = tid >> 7;     // B: col (n), k-quad parity

    float acc[4][4][4];
    #pragma unroll
    for (int i = 0; i < 4; i++)
        #pragma unroll
        for (int j = 0; j < 4; j++)
            #pragma unroll
            for (int e = 0; e < 4; e++) acc[i][j][e] = 0.0f;

    float4 aReg[8];
    float  bReg[8][4];

    const float* Abase = A + (size_t)(bm + a_row) * lda;
    const float* Bbase = B + bn + b_n;
    const int nkt = K / BK;

    auto LDG = [&](int t) {
        #pragma unroll
        for (int j = 0; j < 8; j++) {
            const int k4 = a_k4b + 2 * j;
            aReg[j] = *reinterpret_cast<const float4*>(Abase + t * BK + k4 * 4);
        }
        #pragma unroll
        for (int j = 0; j < 8; j++) {
            const int kq = b_kqb + 2 * j;
            #pragma unroll
            for (int i = 0; i < 4; i++)
                bReg[j][i] = Bbase[(size_t)(t * BK + kq * 4 + i) * ldb];
        }
    };

    auto STS = [&](int s) {
        char* st = smem + s * STAGE_BYTES;
        #pragma unroll
        for (int j = 0; j < 8; j++) {
            const int k4 = a_k4b + 2 * j;
            float4 v = aReg[j];
            if (SQ) { v.x *= v.x; v.y *= v.y; v.z *= v.z; v.w *= v.w; }
            uint32_t h0, l0, h1, l1;
            split2(v.x, v.y, h0, l0);
            split2(v.z, v.w, h1, l1);
            const int off = a_row * PITCH_B + k4 * 8;
            *reinterpret_cast<uint2*>(st + off) = make_uint2(h0, h1);
            *reinterpret_cast<uint2*>(st + TILE_BYTES + off) = make_uint2(l0, l1);
        }
        #pragma unroll
        for (int j = 0; j < 8; j++) {
            const int kq = b_kqb + 2 * j;
            uint32_t h0, l0, h1, l1;
            split2(bReg[j][0], bReg[j][1], h0, l0);
            split2(bReg[j][2], bReg[j][3], h1, l1);
            const int off = b_n * PITCH_B + kq * 8;
            *reinterpret_cast<uint2*>(st + 2 * TILE_BYTES + off) = make_uint2(h0, h1);
            *reinterpret_cast<uint2*>(st + 3 * TILE_BYTES + off) = make_uint2(l0, l1);
        }
    };

    LDG(0);
    STS(0);
    __syncthreads();

    for (int t = 0; t < nkt; t++) {
        const int s = t & 1;
        const char* st = smem + s * STAGE_BYTES;
        const bool has_next = (t + 1 < nkt);
        if (has_next) LDG(t + 1);

        #pragma unroll
        for (int kk = 0; kk < 4; kk++) {
            const int c0 = (kk * 16 + 2 * quad) * 2;
            const int c8 = c0 + 16;

            uint32_t ah[4][4], al[4][4], bh[4][2], bl[4][2];
            #pragma unroll
            for (int mt = 0; mt < 4; mt++) {
                const int r0 = (wm + mt * 16 + grp) * PITCH_B;
                const int r8 = r0 + 8 * PITCH_B;
                ah[mt][0] = *reinterpret_cast<const uint32_t*>(st + r0 + c0);
                ah[mt][1] = *reinterpret_cast<const uint32_t*>(st + r8 + c0);
                ah[mt][2] = *reinterpret_cast<const uint32_t*>(st + r0 + c8);
                ah[mt][3] = *reinterpret_cast<const uint32_t*>(st + r8 + c8);
                al[mt][0] = *reinterpret_cast<const uint32_t*>(st + TILE_BYTES + r0 + c0);
                al[mt][1] = *reinterpret_cast<const uint32_t*>(st + TILE_BYTES + r8 + c0);
                al[mt][2] = *reinterpret_cast<const uint32_t*>(st + TILE_BYTES + r0 + c8);
                al[mt][3] = *reinterpret_cast<const uint32_t*>(st + TILE_BYTES + r8 + c8);
            }
            #pragma unroll
            for (int nt = 0; nt < 4; nt++) {
                const int r = (wn + nt * 8 + grp) * PITCH_B;
                bh[nt][0] = *reinterpret_cast<const uint32_t*>(st + 2 * TILE_BYTES + r + c0);
                bh[nt][1] = *reinterpret_cast<const uint32_t*>(st + 2 * TILE_BYTES + r + c8);
                bl[nt][0] = *reinterpret_cast<const uint32_t*>(st + 3 * TILE_BYTES + r + c0);
                bl[nt][1] = *reinterpret_cast<const uint32_t*>(st + 3 * TILE_BYTES + r + c8);
            }
            #pragma unroll
            for (int mt = 0; mt < 4; mt++) {
                #pragma unroll
                for (int nt = 0; nt < 4; nt++) {
                    mma16816(acc[mt][nt], ah[mt][0], ah[mt][1], ah[mt][2], ah[mt][3],
                             bh[nt][0], bh[nt][1]);
                    mma16816(acc[mt][nt], ah[mt][0], ah[mt][1], ah[mt][2], ah[mt][3],
                             bl[nt][0], bl[nt][1]);
                    mma16816(acc[mt][nt], al[mt][0], al[mt][1], al[mt][2], al[mt][3],
                             bh[nt][0], bh[nt][1]);
                }
            }
        }

        if (has_next) STS(s ^ 1);
        __syncthreads();
    }

    // epilogue
    #pragma unroll
    for (int nt = 0; nt < 4; nt++) {
        const int col = bn + wn + nt * 8 + 2 * quad;
        float bb0 = 0.0f, bb1 = 0.0f;
        if (EPI) { bb0 = bias[col]; bb1 = bias[col + 1]; }
        #pragma unroll
        for (int mt = 0; mt < 4; mt++) {
            const int row = bm + wm + mt * 16 + grp;
            float2 v01 = make_float2(acc[mt][nt][0], acc[mt][nt][1]);
            float2 v23 = make_float2(acc[mt][nt][2], acc[mt][nt][3]);
            if (EPI) {
                v01.x += bb0; v01.y += bb1;
                v23.x += bb0; v23.y += bb1;
                v01.x = v01.x > 0.0f ? v01.x : expm1f(v01.x);
                v01.y = v01.y > 0.0f ? v01.y : expm1f(v01.y);
                v23.x = v23.x > 0.0f ? v23.x : expm1f(v23.x);
                v23.y = v23.y > 0.0f ? v23.y : expm1f(v23.y);
            }
            *reinterpret_cast<float2*>(C + (size_t)row * ldc + col) = v01;
            *reinterpret_cast<float2*>(C + (size_t)(row + 8) * ldc + col) = v23;
        }
    }
}

extern "C" void kernel_launch(void* const* d_in, const int* in_sizes, int n_in,
                              void* d_out, int out_size)
{
    const float* input  = (const float*)d_in[0];  // [8192, 512]
    const float* adj    = (const float*)d_in[1];  // [8192, 8192]
    const float* weight = (const float*)d_in[2];  // [512, 256]
    const float* bias   = (const float*)d_in[3];  // [256]
    float* out = (float*)d_out;                   // [8192, 256]

    float* support = nullptr;
    cudaGetSymbolAddress((void**)&support, g_support);

    cudaFuncSetAttribute(mma_gemm<false, false>,
                         cudaFuncAttributeMaxDynamicSharedMemorySize, SMEM_BYTES);
    cudaFuncSetAttribute(mma_gemm<true, true>,
                         cudaFuncAttributeMaxDynamicSharedMemorySize, SMEM_BYTES);

    dim3 grid(OUT_F / BN, N_NODES / BM);  // (2, 64) = 128 CTAs

    // GEMM 1: support = input @ weight   (8192 x 512 x 256)
    mma_gemm<false, false><<<grid, 256, SMEM_BYTES>>>(
        input, weight, nullptr, support, IN_F, IN_F, OUT_F, OUT_F);

    // GEMM 2: out = ELU( (adj**2) @ support + bias )   (8192 x 8192 x 256)
    mma_gemm<true, true><<<grid, 256, SMEM_BYTES>>>(
        adj, support, bias, out, N_NODES, N_NODES, OUT_F, OUT_F);
}